// round 13
// baseline (speedup 1.0000x reference)
#include <cuda_runtime.h>
#include <cstdint>
#include <cstddef>

#define HDIM   128
#define GDIM   512      // 4*H
#define BATCH  256
#define SEQ    512
#define DIN    80
#define EMB    256
#define KRP    24       // weight k-pairs per column in REGISTERS (k in [0,48))
#define KSPP   40       // weight k-pairs per column in SMEM (k in [48,128))
#define WROW   82       // float2 stride per thread smem-weight row (80 used + 2 pad; 656B = 41 16B-chunks, odd -> conflict-free)
#define NSEG   4
#define TSEG   128      // steps per lstm segment launch
#define LOG2E  1.4426950408889634f
#define C2LOG2E 2.8853900817779268f

typedef unsigned long long u64;

// ---------------- device scratch (no allocations allowed) ----------------
__device__ float g_G[(size_t)BATCH * SEQ * GDIM];    // gate pre-activations (input part, prescaled)
__device__ float g_hout[(size_t)BATCH * SEQ * HDIM]; // per-step h_out
__device__ float g_Wc[GDIM * DIN];                   // fused + prescaled  W_ih @ W_in
__device__ float g_bc[GDIM];                         // fused + prescaled  bias
__device__ float2 g_WTrp[KRP * GDIM];                // reg-weight pairs: [p][j] (prescaled)
__device__ float2 g_WTp[GDIM * KSPP];                // smem-weight pairs: [j][p-KRP] (prescaled)
// LSTM state carried between segment launches
__device__ float g_hst[BATCH * HDIM];
__device__ float g_cst[BATCH * HDIM];
__device__ float g_hsA[BATCH * HDIM];
__device__ float g_hsB[BATCH * HDIM];
__device__ float g_csA[BATCH * HDIM];
__device__ float g_csB[BATCH * HDIM];

// ---------------- f32x2 helpers ----------------
__device__ __forceinline__ void fma2(u64& d, u64 a, u64 b) {
    asm("fma.rn.f32x2 %0, %1, %2, %0;" : "+l"(d) : "l"(a), "l"(b));
}
__device__ __forceinline__ u64 pack2(float lo, float hi) {
    u64 r; asm("mov.b64 %0, {%1, %2};" : "=l"(r) : "f"(lo), "f"(hi)); return r;
}
__device__ __forceinline__ u64 dup2(float x) {
    u64 r; asm("mov.b64 %0, {%1, %1};" : "=l"(r) : "f"(x)); return r;
}
__device__ __forceinline__ float2 unpack2(u64 v) {
    float2 r; asm("mov.b64 {%0, %1}, %2;" : "=f"(r.x), "=f"(r.y) : "l"(v)); return r;
}

// ---------------- fast activation primitives (inputs prescaled by log2e) ----------------
__device__ __forceinline__ float ex2f(float x) {
    float r; asm("ex2.approx.f32 %0, %1;" : "=f"(r) : "f"(x)); return r;
}
__device__ __forceinline__ float rcpf(float x) {
    float r; asm("rcp.approx.f32 %0, %1;" : "=f"(r) : "f"(x)); return r;
}
__device__ __forceinline__ float sig_p(float g)  { return rcpf(1.0f + ex2f(-g)); }
__device__ __forceinline__ float tanh_p(float g) { return fmaf(-2.0f, rcpf(ex2f(g) + 1.0f), 1.0f); }

// ---------------- kernel 0: fold W_in into W_ih, prescale, pack W_hh^T ----------------
__global__ void combine_kernel(const float* __restrict__ W_in, const float* __restrict__ b_in,
                               const float* __restrict__ W_ih, const float* __restrict__ b_ih,
                               const float* __restrict__ W_hh, const float* __restrict__ b_hh) {
    __shared__ float wih[EMB];
    int j = blockIdx.x;           // 0..511 (gate column)
    int tid = threadIdx.x;        // 128 threads (= k index)
    float s = ((j >> 7) == 2) ? C2LOG2E : LOG2E;   // g-gate rows get 2*log2e
    for (int e = tid; e < EMB; e += 128) wih[e] = W_ih[j * EMB + e];
    if (!(tid & 1)) {
        float2 wp = make_float2(s * W_hh[j * HDIM + tid], s * W_hh[j * HDIM + tid + 1]);
        int p = tid >> 1;                // pair index 0..63
        if (p < KRP) g_WTrp[p * GDIM + j] = wp;
        else         g_WTp[j * KSPP + (p - KRP)] = wp;
    }
    __syncthreads();
    if (tid < DIN) {
        float acc = 0.f;
        #pragma unroll 8
        for (int e = 0; e < EMB; e++) acc = fmaf(wih[e], W_in[e * DIN + tid], acc);
        g_Wc[j * DIN + tid] = s * acc;
    }
    if (tid == 96) {
        float acc = b_ih[j] + b_hh[j];
        #pragma unroll 8
        for (int e = 0; e < EMB; e++) acc = fmaf(wih[e], b_in[e], acc);
        g_bc[j] = s * acc;
    }
}

// ---------------- kernel 1: G[m][j] = x[m][:] . Wc[j][:] + bc[j] ----------------
__global__ void __launch_bounds__(256, 2) gemm_kernel(const float* __restrict__ x) {
    __shared__ float As[40][132];
    __shared__ float Bs[40][132];
    __shared__ float bcs[128];

    int tid = threadIdx.x;
    int n0 = blockIdx.x * 128;
    int m0 = blockIdx.y * 128;
    if (tid < 128) bcs[tid] = g_bc[n0 + tid];
    int tr = tid >> 4, tc = tid & 15;

    u64 acc[8][4];
    #pragma unroll
    for (int i = 0; i < 8; i++)
        #pragma unroll
        for (int j = 0; j < 4; j++) acc[i][j] = 0ull;

    for (int kt = 0; kt < 2; kt++) {
        #pragma unroll
        for (int r = 0; r < 5; r++) {
            int idx = tid + r * 256;
            int row = idx / 10;
            int c4  = idx - row * 10;
            float4 xa = *(const float4*)&x[(size_t)(m0 + row) * DIN + kt * 40 + c4 * 4];
            float4 wb = *(const float4*)&g_Wc[(n0 + row) * DIN + kt * 40 + c4 * 4];
            As[c4 * 4 + 0][row] = xa.x; As[c4 * 4 + 1][row] = xa.y;
            As[c4 * 4 + 2][row] = xa.z; As[c4 * 4 + 3][row] = xa.w;
            Bs[c4 * 4 + 0][row] = wb.x; Bs[c4 * 4 + 1][row] = wb.y;
            Bs[c4 * 4 + 2][row] = wb.z; Bs[c4 * 4 + 3][row] = wb.w;
        }
        __syncthreads();
        #pragma unroll 4
        for (int k = 0; k < 40; k++) {
            float4 a0 = *(const float4*)&As[k][tr * 8];
            float4 a1 = *(const float4*)&As[k][tr * 8 + 4];
            float4 b0 = *(const float4*)&Bs[k][tc * 8];
            float4 b1 = *(const float4*)&Bs[k][tc * 8 + 4];
            u64 ap[8] = {dup2(a0.x), dup2(a0.y), dup2(a0.z), dup2(a0.w),
                         dup2(a1.x), dup2(a1.y), dup2(a1.z), dup2(a1.w)};
            u64 bp[4] = {pack2(b0.x, b0.y), pack2(b0.z, b0.w),
                         pack2(b1.x, b1.y), pack2(b1.z, b1.w)};
            #pragma unroll
            for (int i = 0; i < 8; i++)
                #pragma unroll
                for (int j = 0; j < 4; j++)
                    fma2(acc[i][j], ap[i], bp[j]);
        }
        __syncthreads();
    }

    float bc0 = bcs[tc * 8 + 0], bc1 = bcs[tc * 8 + 1], bc2 = bcs[tc * 8 + 2], bc3 = bcs[tc * 8 + 3];
    float bc4 = bcs[tc * 8 + 4], bc5 = bcs[tc * 8 + 5], bc6 = bcs[tc * 8 + 6], bc7 = bcs[tc * 8 + 7];
    #pragma unroll
    for (int i = 0; i < 8; i++) {
        float* orow = g_G + (size_t)(m0 + tr * 8 + i) * GDIM + n0 + tc * 8;
        float2 v0 = unpack2(acc[i][0]), v1 = unpack2(acc[i][1]);
        float2 v2 = unpack2(acc[i][2]), v3 = unpack2(acc[i][3]);
        *(float4*)orow       = make_float4(v0.x + bc0, v0.y + bc1, v1.x + bc2, v1.y + bc3);
        *(float4*)(orow + 4) = make_float4(v2.x + bc4, v2.y + bc5, v3.x + bc6, v3.y + bc7);
    }
}

// ---------------- kernel 2: LSTM recurrence segment ----------------
// 128 blocks x 256 threads (8 warps -> 2 per SMSP). Weights read ONCE.
// Thread (half = tid>>7, u = tid&127) owns columns cA = half*128+u and
// cB = cA+256 for BOTH batch rows (4 f32x2 accumulators, 256 fma2/step).
// half=0 owns gates (i,g) of unit u, half=1 owns (f,o).
// Phase B is ROW-SPLIT: half=0 runs row 0's activation chain, half=1 runs
// row 1's -- each publishes its other-row gate pair (one float2), so the
// MUFU chain per thread is halved and spread over all 8 warps.
// Weight split 24 reg-pairs + 40 smem-pairs per column frees ~32 more
// registers for ptxas LDS software-pipelining (the R11 lever, bigger dose).
__global__ void __launch_bounds__(256, 1) lstm_kernel(const float* __restrict__ w_time, int t0) {
    extern __shared__ float smem[];
    float*  hbuf = smem;                       // [2 parity][2 rows][128]
    float2* fxA  = (float2*)(smem + 512);      // half=0 publishes (i_r1, g_r1)
    float2* fxB  = (float2*)(smem + 768);      // half=1 publishes (f_r0, o_r0)
    float2* Wsp  = (float2*)(smem + 1024);     // [256 thread rows][WROW]

    int tid  = threadIdx.x;                    // 0..255
    int half = tid >> 7;                       // 0: (i,g)/row0; 1: (f,o)/row1
    int u    = tid & 127;                      // hidden unit
    int cA   = (half << 7) + u;                // gate i (half=0) / f (half=1)
    int cB   = cA + 256;                       // gate g (half=0) / o (half=1)
    int b0   = blockIdx.x * 2;

    // stage this thread's smem weight row: [cA pairs 24..63][cB pairs 24..63]
    {
        const float4* srcA = (const float4*)(g_WTp + cA * KSPP);
        const float4* srcB = (const float4*)(g_WTp + cB * KSPP);
        float4* dst = (float4*)(Wsp + tid * WROW);
        #pragma unroll
        for (int i = 0; i < KSPP / 2; i++) dst[i] = srcA[i];
        #pragma unroll
        for (int i = 0; i < KSPP / 2; i++) dst[KSPP / 2 + i] = srcB[i];
    }
    // register weights: 24 pairs per column (coalesced float2 over j)
    u64 wrA[KRP], wrB[KRP];
    #pragma unroll
    for (int p = 0; p < KRP; p++) {
        float2 a = g_WTrp[p * GDIM + cA];
        float2 b = g_WTrp[p * GDIM + cB];
        wrA[p] = pack2(a.x, a.y);
        wrB[p] = pack2(b.x, b.y);
    }

    // carried state: this thread owns batch row (b0 + half), hidden unit u
    int si = (b0 + half) * HDIM + u;
    float cc, hsA, hsB, csA, csB;
    {
        int par0 = t0 & 1;
        if (t0 == 0) {
            cc = 0.f; hsA = hsB = csA = csB = 0.f;
            hbuf[par0 * 256 + half * 128 + u] = 0.f;
        } else {
            cc = g_cst[si];
            hsA = g_hsA[si]; hsB = g_hsB[si];
            csA = g_csA[si]; csB = g_csB[si];
            hbuf[par0 * 256 + half * 128 + u] = g_hst[si];
        }
    }
    float wt0 = w_time[0], wt1 = w_time[1], wt2 = w_time[2];
    __syncthreads();

    // G streams: (col, row) x 4 (dot products still cover BOTH rows)
    const float* GA0 = g_G + (size_t)b0 * SEQ * GDIM + cA;
    const float* GB0 = GA0 + 256;
    const float* GA1 = GA0 + (size_t)SEQ * GDIM;
    const float* GB1 = GA1 + 256;
    float* hoP = g_hout + (size_t)(b0 + half) * SEQ * HDIM + u;   // own row's h_out

    const ulonglong2* WrowA = (const ulonglong2*)(Wsp + tid * WROW);          // 20 x 2 pairs
    const ulonglong2* WrowB = (const ulonglong2*)(Wsp + tid * WROW + KSPP);   // 20 x 2 pairs

    float preA0 = GA0[(size_t)t0 * GDIM], preB0 = GB0[(size_t)t0 * GDIM];
    float preA1 = GA1[(size_t)t0 * GDIM], preB1 = GB1[(size_t)t0 * GDIM];

    int slot = t0 % 3;
    for (int t = t0; t < t0 + TSEG; t++) {
        u64 aA0 = pack2(preA0, 0.f), aB0 = pack2(preB0, 0.f);
        u64 aA1 = pack2(preA1, 0.f), aB1 = pack2(preB1, 0.f);
        int tn = (t + 1 < SEQ) ? (t + 1) : t;     // prefetch next step's G
        preA0 = GA0[(size_t)tn * GDIM];
        preB0 = GB0[(size_t)tn * GDIM];
        preA1 = GA1[(size_t)tn * GDIM];
        preB1 = GB1[(size_t)tn * GDIM];

        const ulonglong2* H0 = (const ulonglong2*)(hbuf + (t & 1) * 256);
        const ulonglong2* H1 = H0 + 32;           // +128 floats
        #pragma unroll
        for (int q = 0; q < 32; q++) {            // pairs 2q, 2q+1 (4 k values)
            ulonglong2 h0 = H0[q];
            ulonglong2 h1 = H1[q];
            u64 wAa, wAb, wBa, wBb;
            if (2 * q < KRP) {                    // q < 12: both pairs from regs
                wAa = wrA[2 * q]; wAb = wrA[2 * q + 1];
                wBa = wrB[2 * q]; wBb = wrB[2 * q + 1];
            } else {                              // smem: 2 pairs per LDS.128
                ulonglong2 wA2 = WrowA[q - KRP / 2];
                ulonglong2 wB2 = WrowB[q - KRP / 2];
                wAa = wA2.x; wAb = wA2.y;
                wBa = wB2.x; wBb = wB2.y;
            }
            fma2(aA0, wAa, h0.x);
            fma2(aA1, wAa, h1.x);
            fma2(aB0, wBa, h0.x);
            fma2(aB1, wBa, h1.x);
            fma2(aA0, wAb, h0.y);
            fma2(aA1, wAb, h1.y);
            fma2(aB0, wBb, h0.y);
            fma2(aB1, wBb, h1.y);
        }

        float2 vA0 = unpack2(aA0), vA1 = unpack2(aA1);
        float2 vB0 = unpack2(aB0), vB1 = unpack2(aB1);
        float gA0 = vA0.x + vA0.y, gA1 = vA1.x + vA1.y;   // col cA, rows 0/1
        float gB0 = vB0.x + vB0.y, gB1 = vB1.x + vB1.y;   // col cB, rows 0/1

        // publish other-row gate pair
        if (half == 0) fxA[u] = make_float2(gA1, gB1);    // (i_r1, g_r1)
        else           fxB[u] = make_float2(gA0, gB0);    // (f_r0, o_r0)
        __syncthreads();                          // barrier 1: partials ready

        {   // phase B: each thread runs ONE row's activation chain
            float2 e = half ? fxA[u] : fxB[u];
            float ig = half ? e.x : gA0;
            float gg = half ? e.y : gB0;
            float fg = half ? gA1 : e.x;
            float og = half ? gB1 : e.y;
            float cn = fmaf(sig_p(fg), cc, sig_p(ig) * tanh_p(gg));
            float hn = sig_p(og) * tanh_p(C2LOG2E * cn);
            float ho_, co_;
            if (slot == 0)      { hsA = hn; csA = cn; ho_ = hn; co_ = cn; }
            else if (slot == 1) { hsB = hn; csB = cn; ho_ = hn; co_ = cn; }
            else {
                ho_ = wt0 * hsA + wt1 * hsB + wt2 * hn;
                co_ = wt0 * csA + wt1 * csB + wt2 * cn;
            }
            cc = co_;
            hbuf[((t + 1) & 1) * 256 + half * 128 + u] = ho_;
            hoP[(size_t)t * HDIM] = ho_;
        }
        slot = (slot == 2) ? 0 : slot + 1;
        __syncthreads();                          // barrier 2: new h published
    }

    // store carried state (each thread owns one row)
    {
        int parE = (t0 + TSEG) & 1;
        g_hst[si] = hbuf[parE * 256 + half * 128 + u];
        g_cst[si] = cc;
        g_hsA[si] = hsA; g_hsB[si] = hsB;
        g_csA[si] = csA; g_csB[si] = csB;
    }
}

// ---------------- kernel 3: logits = hout @ W_br^T + b_br, then log_softmax ----------------
__global__ void __launch_bounds__(256) logits_kernel(const float* __restrict__ W_br,
                                                     const float* __restrict__ b_br,
                                                     float* __restrict__ out) {
    __shared__ float wbr[4 * HDIM];
    __shared__ float bb[4];
    int tid = threadIdx.x;
    for (int i = tid; i < 4 * HDIM; i += 256) wbr[i] = W_br[i];
    if (tid < 4) bb[tid] = b_br[tid];
    __syncthreads();

    int warp = tid >> 5, lane = tid & 31;
    size_t row = (size_t)blockIdx.x * 8 + warp;
    float4 hv = *(const float4*)(g_hout + row * HDIM + lane * 4);

    float p[4];
    #pragma unroll
    for (int o = 0; o < 4; o++) {
        float4 w = *(const float4*)&wbr[o * HDIM + lane * 4];
        p[o] = fmaf(hv.x, w.x, fmaf(hv.y, w.y, fmaf(hv.z, w.z, hv.w * w.w)));
    }
    #pragma unroll
    for (int off = 16; off; off >>= 1) {
        #pragma unroll
        for (int o = 0; o < 4; o++) p[o] += __shfl_xor_sync(0xffffffffu, p[o], off);
    }
    if (lane == 0) {
        float x0 = p[0] + bb[0], x1 = p[1] + bb[1], x2 = p[2] + bb[2], x3 = p[3] + bb[3];
        float m = fmaxf(fmaxf(x0, x1), fmaxf(x2, x3));
        float s = __expf(x0 - m) + __expf(x1 - m) + __expf(x2 - m) + __expf(x3 - m);
        float l = __logf(s);
        *(float4*)(out + row * 4) = make_float4(x0 - m - l, x1 - m - l, x2 - m - l, x3 - m - l);
    }
}

// ---------------- launch ----------------
extern "C" void kernel_launch(void* const* d_in, const int* in_sizes, int n_in,
                              void* d_out, int out_size) {
    const float* x      = (const float*)d_in[0];
    const float* W_in   = (const float*)d_in[1];
    const float* b_in   = (const float*)d_in[2];
    const float* W_ih   = (const float*)d_in[3];
    const float* b_ih   = (const float*)d_in[4];
    const float* W_hh   = (const float*)d_in[5];
    const float* b_hh   = (const float*)d_in[6];
    const float* w_time = (const float*)d_in[7];
    const float* W_br   = (const float*)d_in[8];
    const float* b_br   = (const float*)d_in[9];
    float* out = (float*)d_out;

    combine_kernel<<<GDIM, 128>>>(W_in, b_in, W_ih, b_ih, W_hh, b_hh);
    gemm_kernel<<<dim3(4, 1024), 256>>>(x);

    // hbuf(512f) + fxA/fxB(512f) + Wsp(256 * WROW float2)
    size_t shmem = 1024 * sizeof(float) + (size_t)256 * WROW * sizeof(float2);  // 172032 B
    cudaFuncSetAttribute(lstm_kernel, cudaFuncAttributeMaxDynamicSharedMemorySize, (int)shmem);
    for (int s = 0; s < NSEG; s++)
        lstm_kernel<<<BATCH / 2, 256, shmem>>>(w_time, s * TSEG);

    logits_kernel<<<(BATCH * SEQ) / 8, 256>>>(W_br, b_br, out);
}